// round 2
// baseline (speedup 1.0000x reference)
#include <cuda_runtime.h>

// Problem constants
#define B_   32
#define H_   56
#define W_   56
#define C_   256
#define GRP  32          // groups
#define ICG  8           // in-channels per group
#define OCG  8           // out-channels per group

// Conv kernel tiling
#define BDIM   128       // threads per block = channels per block
#define CHALF  128       // channels handled per block
#define NGL    16        // local groups per block
#define ROWW   60        // padded smem row length (56 cols + 2 halo + align pad)
#define CHPAD  144       // 16 groups * 9 (stride-9 channel padding -> conflict-free)
#define SMEM_FLOATS (3 * CHPAD * ROWW)       // 25920
#define SMEM_BYTES  (SMEM_FLOATS * 4)        // 103680

#define NROWBLK (B_ * H_)                    // 1792 (n,h) row-blocks per channel half

// Scratch (device globals; no allocation allowed)
__device__ float g_psum  [2 * NROWBLK * CHALF];
__device__ float g_psumsq[2 * NROWBLK * CHALF];
__device__ float g_scale[C_];
__device__ float g_shift[C_];

// ---------------------------------------------------------------------------
// Kernel 1: grouped conv row-block + per-block channel partial sums
// grid = (56, 32, 2): (h, n, channel-half); block = 128 threads (1 per out ch)
// ---------------------------------------------------------------------------
__global__ __launch_bounds__(BDIM, 2)
void conv_kernel(const float* __restrict__ x, const float* __restrict__ w,
                 const float* __restrict__ bias, float* __restrict__ y)
{
    extern __shared__ float smem[];
    const int t  = threadIdx.x;        // 0..127  (local out channel)
    const int h  = blockIdx.x;         // 0..55
    const int n  = blockIdx.y;         // 0..31
    const int z  = blockIdx.z;         // 0..1
    const int cbase = z * CHALF;
    const int o  = cbase + t;          // global out channel
    const int gl = t >> 3;             // local group 0..15

    // Zero smem (covers halo columns / out-of-image rows)
    {
        float4* s4 = (float4*)smem;
        const float4 z4 = make_float4(0.f, 0.f, 0.f, 0.f);
        #pragma unroll 4
        for (int idx = t; idx < SMEM_FLOATS / 4; idx += BDIM) s4[idx] = z4;
    }

    // Load all 72 weights for this output channel into registers.
    // w layout HWIO: flat k = (dh*3 + dw)*8 + i, element w[k*256 + o]
    float wr[72];
    #pragma unroll
    for (int k = 0; k < 72; k++) wr[k] = __ldg(&w[k * C_ + o]);

    __syncthreads();

    // Cooperative load of 3 input rows (h-1, h, h+1) into smem.
    // smem layout: [(dh*CHPAD + g*9 + i)*ROWW + (col+1)]
    #pragma unroll
    for (int dh = 0; dh < 3; dh++) {
        const int hh = h + dh - 1;
        if (hh < 0 || hh >= H_) continue;
        const float4* src = (const float4*)(x + ((size_t)(n * H_ + hh) * W_) * C_ + cbase);
        // 56 cols * 32 float4 (=128 floats) per row
        for (int f = t; f < W_ * 32; f += BDIM) {
            const int col = f >> 5;            // 0..55
            const int c4  = f & 31;            // 0..31
            const float4 v = __ldg(&src[col * (C_ / 4) + c4]);
            const int g    = c4 >> 1;          // local group
            const int ioff = (c4 & 1) * 4;     // 0 or 4
            float* dst = smem + (size_t)(dh * CHPAD + g * 9 + ioff) * ROWW + (col + 1);
            dst[0 * ROWW] = v.x;
            dst[1 * ROWW] = v.y;
            dst[2 * ROWW] = v.z;
            dst[3 * ROWW] = v.w;
        }
    }
    __syncthreads();

    const float bo = __ldg(&bias[o]);
    float lsum = 0.f, lsumsq = 0.f;
    float* yrow = y + ((size_t)(n * H_ + h) * W_) * C_ + o;
    const float* sg = smem + (size_t)(gl * 9) * ROWW;   // group base

    for (int wb = 0; wb < W_; wb += 8) {
        float acc[8];
        #pragma unroll
        for (int j = 0; j < 8; j++) acc[j] = 0.f;

        #pragma unroll
        for (int dh = 0; dh < 3; dh++) {
            #pragma unroll
            for (int ii = 0; ii < 8; ii++) {
                const float* row = sg + (size_t)(dh * CHPAD + ii) * ROWW + wb;
                // 10 contiguous floats, 16B aligned (ROWW=60 divisible by 4, wb mult of 8)
                const float4 a  = *(const float4*)(row);
                const float4 b4 = *(const float4*)(row + 4);
                const float2 c2 = *(const float2*)(row + 8);
                const float xv[10] = {a.x, a.y, a.z, a.w,
                                      b4.x, b4.y, b4.z, b4.w,
                                      c2.x, c2.y};
                const float w0 = wr[dh * 24 + 0 + ii];
                const float w1 = wr[dh * 24 + 8 + ii];
                const float w2 = wr[dh * 24 + 16 + ii];
                #pragma unroll
                for (int j = 0; j < 8; j++)
                    acc[j] += xv[j] * w0 + xv[j + 1] * w1 + xv[j + 2] * w2;
            }
        }

        #pragma unroll
        for (int j = 0; j < 8; j++) {
            const float v = acc[j] + bo;
            yrow[(size_t)(wb + j) * C_] = v;
            lsum   += v;
            lsumsq += v * v;
        }
    }

    // Deterministic partial-sum slots (no atomics)
    const int blin = (z * NROWBLK + n * H_ + h) * CHALF + t;
    g_psum[blin]   = lsum;
    g_psumsq[blin] = lsumsq;
}

// ---------------------------------------------------------------------------
// Kernel 2: finalize batch stats -> scale/shift per channel (1 block, 256 thr)
// ---------------------------------------------------------------------------
__global__ void stats_kernel(const float* __restrict__ gamma,
                             const float* __restrict__ beta)
{
    const int o = threadIdx.x;         // 0..255
    const int z = o >> 7;
    const int t = o & (CHALF - 1);

    float s0 = 0.f, s1 = 0.f, s2 = 0.f, s3 = 0.f;
    float q0 = 0.f, q1 = 0.f, q2 = 0.f, q3 = 0.f;
    const float* ps = g_psum   + (size_t)z * NROWBLK * CHALF + t;
    const float* pq = g_psumsq + (size_t)z * NROWBLK * CHALF + t;
    #pragma unroll 4
    for (int r = 0; r < NROWBLK; r += 4) {
        s0 += ps[(r + 0) * CHALF];  q0 += pq[(r + 0) * CHALF];
        s1 += ps[(r + 1) * CHALF];  q1 += pq[(r + 1) * CHALF];
        s2 += ps[(r + 2) * CHALF];  q2 += pq[(r + 2) * CHALF];
        s3 += ps[(r + 3) * CHALF];  q3 += pq[(r + 3) * CHALF];
    }
    const float s = (s0 + s1) + (s2 + s3);
    const float q = (q0 + q1) + (q2 + q3);

    const float Ninv = 1.0f / (float)(B_ * H_ * W_);
    const float mean = s * Ninv;
    const float var  = q * Ninv - mean * mean;
    const float sc   = gamma[o] * rsqrtf(var + 1e-5f);
    g_scale[o] = sc;
    g_shift[o] = beta[o] - mean * sc;
}

// ---------------------------------------------------------------------------
// Kernel 3: in-place normalize + ReLU on y (float4 vectorized)
// ---------------------------------------------------------------------------
__global__ void norm_kernel(float* __restrict__ y, int n4)
{
    const int idx = blockIdx.x * blockDim.x + threadIdx.x;
    if (idx >= n4) return;
    float4 v = ((float4*)y)[idx];
    const int c = (idx * 4) & (C_ - 1);
    v.x = fmaxf(v.x * g_scale[c + 0] + g_shift[c + 0], 0.f);
    v.y = fmaxf(v.y * g_scale[c + 1] + g_shift[c + 1], 0.f);
    v.z = fmaxf(v.z * g_scale[c + 2] + g_shift[c + 2], 0.f);
    v.w = fmaxf(v.w * g_scale[c + 3] + g_shift[c + 3], 0.f);
    ((float4*)y)[idx] = v;
}

// ---------------------------------------------------------------------------
extern "C" void kernel_launch(void* const* d_in, const int* in_sizes, int n_in,
                              void* d_out, int out_size)
{
    const float* x     = (const float*)d_in[0];
    const float* w     = (const float*)d_in[1];
    const float* b     = (const float*)d_in[2];
    const float* gamma = (const float*)d_in[3];
    const float* beta  = (const float*)d_in[4];
    float* out = (float*)d_out;

    // Opt-in to >48KB dynamic smem (idempotent, host-side, capture-safe)
    cudaFuncSetAttribute(conv_kernel,
                         cudaFuncAttributeMaxDynamicSharedMemorySize, SMEM_BYTES);

    dim3 grid(H_, B_, 2);
    conv_kernel<<<grid, BDIM, SMEM_BYTES>>>(x, w, b, out);

    stats_kernel<<<1, C_>>>(gamma, beta);

    const int n4 = out_size / 4;
    norm_kernel<<<(n4 + 255) / 256, 256>>>(out, n4);
}

// round 3
// speedup vs baseline: 2.1776x; 2.1776x over previous
#include <cuda_runtime.h>

// Problem constants
#define B_   32
#define H_   56
#define W_   56
#define C_   256

// Conv tiling
#define BDIM   256       // 2 column-teams x 128 channels
#define CHALF  128       // channels per block
#define ROWW   60        // padded smem row length
#define CHPAD  144       // 16 groups * 9 (stride-9 padding -> conflict-free)
#define SLOT   (CHPAD * ROWW)                // floats per row-slot
#define SMEM_FLOATS (3 * SLOT)               // 25920
#define SMEM_BYTES  (SMEM_FLOATS * 4)        // 103680
#define RPB    4         // output rows per block

#define NPART  896       // partials per channel: 14 row-blocks * 32 n * 2 teams

__device__ float g_psum  [C_ * NPART];
__device__ float g_psumsq[C_ * NPART];
__device__ float g_scale[C_];
__device__ float g_shift[C_];

typedef unsigned long long u64;

__device__ __forceinline__ u64 pack2(float lo, float hi) {
    u64 r; asm("mov.b64 %0, {%1, %2};" : "=l"(r) : "f"(lo), "f"(hi)); return r;
}
__device__ __forceinline__ u64 fma2(u64 a, u64 b, u64 c) {
    u64 d; asm("fma.rn.f32x2 %0, %1, %2, %3;" : "=l"(d) : "l"(a), "l"(b), "l"(c)); return d;
}
__device__ __forceinline__ u64 f2u(float2 v) { return *reinterpret_cast<const u64*>(&v); }
__device__ __forceinline__ float u2lo(u64 v) { return __uint_as_float((unsigned)v); }
__device__ __forceinline__ float u2hi(u64 v) { return __uint_as_float((unsigned)(v >> 32)); }

// Load one input row hh into its rolling slot ((hh+3)%3). 256 threads.
__device__ __forceinline__ void load_row(float* smem, const float* __restrict__ x,
                                         int n, int hh, int cbase, int t)
{
    float* slot = smem + (size_t)((hh + 3) % 3) * SLOT;
    const float4* src = (const float4*)(x + ((size_t)(n * H_ + hh) * W_) * C_ + cbase);
    #pragma unroll
    for (int it = 0; it < 7; it++) {                  // 56*32/256 = 7
        const int f   = t + it * BDIM;
        const int col = f >> 5;
        const int c4  = f & 31;
        const float4 v = __ldg(&src[col * (C_ / 4) + c4]);
        const int g    = c4 >> 1;
        const int ioff = (c4 & 1) * 4;
        float* dst = slot + (size_t)(g * 9 + ioff) * ROWW + (col + 1);
        dst[0 * ROWW] = v.x;  dst[1 * ROWW] = v.y;
        dst[2 * ROWW] = v.z;  dst[3 * ROWW] = v.w;
    }
}

// Zero the data columns of slot for (virtual) row hh (OOB padding row).
__device__ __forceinline__ void zero_row(float* smem, int hh, int t)
{
    float* slot = smem + (size_t)((hh + 3) % 3) * SLOT;
    #pragma unroll
    for (int it = 0; it < 7; it++) {
        const int f   = t + it * BDIM;
        const int col = f >> 5;
        const int c4  = f & 31;
        const int g    = c4 >> 1;
        const int ioff = (c4 & 1) * 4;
        float* dst = slot + (size_t)(g * 9 + ioff) * ROWW + (col + 1);
        dst[0 * ROWW] = 0.f;  dst[1 * ROWW] = 0.f;
        dst[2 * ROWW] = 0.f;  dst[3 * ROWW] = 0.f;
    }
}

// ---------------------------------------------------------------------------
// Kernel 1: grouped conv, 4 rows per block, rolling 3-slot window, f32x2 math
// grid = (14, 32, 2): (row-block, n, channel-half); block = 256 threads
// ---------------------------------------------------------------------------
__global__ __launch_bounds__(BDIM, 2)
void conv_kernel(const float* __restrict__ x, const float* __restrict__ w,
                 const float* __restrict__ bias, float* __restrict__ y)
{
    extern __shared__ float smem[];
    const int t    = threadIdx.x;
    const int ch   = t & (CHALF - 1);     // local out channel 0..127
    const int team = t >> 7;              // column team 0/1
    const int bx   = blockIdx.x;          // row-block 0..13
    const int n    = blockIdx.y;
    const int z    = blockIdx.z;
    const int cbase = z * CHALF;
    const int o    = cbase + ch;          // global out channel
    const int gl   = ch >> 3;             // local group 0..15
    const int h0   = bx * RPB;

    // Zero smem once (covers halo cols + OOB rows)
    {
        float4* s4 = (float4*)smem;
        const float4 z4 = make_float4(0.f, 0.f, 0.f, 0.f);
        for (int idx = t; idx < SMEM_FLOATS / 4; idx += BDIM) s4[idx] = z4;
    }

    // 72 weights for this out channel (HWIO: element w[k*256 + o], k=(dh*3+kw)*8+i)
    float wr[72];
    #pragma unroll
    for (int k = 0; k < 72; k++) wr[k] = __ldg(&w[k * C_ + o]);
    const float bo = __ldg(&bias[o]);

    __syncthreads();
    // Prologue: rows h0-1 (if valid; else stays zero), h0, h0+1
    if (h0 > 0) load_row(smem, x, n, h0 - 1, cbase, t);
    load_row(smem, x, n, h0,     cbase, t);
    load_row(smem, x, n, h0 + 1, cbase, t);
    __syncthreads();

    float lsum = 0.f, lsumsq = 0.f;

    for (int r = 0; r < RPB; r++) {
        const int hr = h0 + r;
        const float* sl[3];
        sl[0] = smem + (size_t)((hr + 2) % 3) * SLOT + (size_t)gl * 9 * ROWW; // row hr-1
        sl[1] = smem + (size_t)((hr    ) % 3) * SLOT + (size_t)gl * 9 * ROWW; // row hr
        sl[2] = smem + (size_t)((hr + 1) % 3) * SLOT + (size_t)gl * 9 * ROWW; // row hr+1
        float* yrow = y + ((size_t)(n * H_ + hr) * W_) * C_ + o;

        #pragma unroll
        for (int wseg = 0; wseg < 2; wseg++) {
            const int segbase = team * 28 + wseg * 14;   // output cols segbase..segbase+13

            u64  acc2[7];
            float accs[14];
            #pragma unroll
            for (int q = 0; q < 7; q++)  acc2[q] = 0ULL;
            #pragma unroll
            for (int j = 0; j < 14; j++) accs[j] = 0.f;

            #pragma unroll
            for (int dh = 0; dh < 3; dh++) {
                const float* base = sl[dh] + segbase;
                #pragma unroll
                for (int ii = 0; ii < 8; ii++) {
                    const float* rowp = base + ii * ROWW;
                    float2 E[8];
                    #pragma unroll
                    for (int k = 0; k < 8; k++)
                        E[k] = *(const float2*)(rowp + 2 * k);

                    const float w0 = wr[dh * 24 + 0 + ii];
                    const float w1 = wr[dh * 24 + 8 + ii];
                    const float w2 = wr[dh * 24 + 16 + ii];
                    const u64 W0 = pack2(w0, w0);
                    const u64 W2 = pack2(w2, w2);

                    #pragma unroll
                    for (int p = 0; p < 7; p++) {
                        acc2[p] = fma2(f2u(E[p]),     W0, acc2[p]);   // kw=0
                        acc2[p] = fma2(f2u(E[p + 1]), W2, acc2[p]);   // kw=2
                        accs[2*p]   = fmaf(E[p].y,     w1, accs[2*p]);     // kw=1
                        accs[2*p+1] = fmaf(E[p + 1].x, w1, accs[2*p+1]);
                    }
                }
            }

            #pragma unroll
            for (int j = 0; j < 14; j++) {
                const int q = j >> 1;
                const float packed = (j & 1) ? u2hi(acc2[q]) : u2lo(acc2[q]);
                const float v = packed + accs[j] + bo;
                yrow[(size_t)(segbase + j) * C_] = v;
                lsum   += v;
                lsumsq += v * v;
            }
        }

        __syncthreads();
        if (r < RPB - 1) {
            const int nxt = hr + 2;
            if (nxt < H_)       load_row(smem, x, n, nxt, cbase, t);
            else if (nxt == H_) zero_row(smem, nxt, t);
        }
        __syncthreads();
    }

    // Channel-major partials for coalesced stats reads
    const int pidx = (bx * 32 + n) * 2 + team;
    g_psum  [(size_t)o * NPART + pidx] = lsum;
    g_psumsq[(size_t)o * NPART + pidx] = lsumsq;
}

// ---------------------------------------------------------------------------
// Kernel 2: stats finalize — one block per channel (256 blocks x 128 threads)
// ---------------------------------------------------------------------------
__global__ void stats_kernel(const float* __restrict__ gamma,
                             const float* __restrict__ beta)
{
    __shared__ float ss[128], sq[128];
    const int o = blockIdx.x;
    const int t = threadIdx.x;

    float s = 0.f, q = 0.f;
    const float* ps = g_psum   + (size_t)o * NPART;
    const float* pq = g_psumsq + (size_t)o * NPART;
    #pragma unroll
    for (int i = t; i < NPART; i += 128) { s += ps[i]; q += pq[i]; }
    ss[t] = s; sq[t] = q;
    __syncthreads();
    #pragma unroll
    for (int st = 64; st > 0; st >>= 1) {
        if (t < st) { ss[t] += ss[t + st]; sq[t] += sq[t + st]; }
        __syncthreads();
    }
    if (t == 0) {
        const float Ninv = 1.0f / (float)(B_ * H_ * W_);
        const float mean = ss[0] * Ninv;
        const float var  = sq[0] * Ninv - mean * mean;
        const float sc   = gamma[o] * rsqrtf(var + 1e-5f);
        g_scale[o] = sc;
        g_shift[o] = beta[o] - mean * sc;
    }
}

// ---------------------------------------------------------------------------
// Kernel 3: in-place normalize + ReLU (float4)
// ---------------------------------------------------------------------------
__global__ void norm_kernel(float* __restrict__ y, int n4)
{
    const int idx = blockIdx.x * blockDim.x + threadIdx.x;
    if (idx >= n4) return;
    float4 v = ((float4*)y)[idx];
    const int c = (idx * 4) & (C_ - 1);
    v.x = fmaxf(v.x * g_scale[c + 0] + g_shift[c + 0], 0.f);
    v.y = fmaxf(v.y * g_scale[c + 1] + g_shift[c + 1], 0.f);
    v.z = fmaxf(v.z * g_scale[c + 2] + g_shift[c + 2], 0.f);
    v.w = fmaxf(v.w * g_scale[c + 3] + g_shift[c + 3], 0.f);
    ((float4*)y)[idx] = v;
}

// ---------------------------------------------------------------------------
extern "C" void kernel_launch(void* const* d_in, const int* in_sizes, int n_in,
                              void* d_out, int out_size)
{
    const float* x     = (const float*)d_in[0];
    const float* w     = (const float*)d_in[1];
    const float* b     = (const float*)d_in[2];
    const float* gamma = (const float*)d_in[3];
    const float* beta  = (const float*)d_in[4];
    float* out = (float*)d_out;

    cudaFuncSetAttribute(conv_kernel,
                         cudaFuncAttributeMaxDynamicSharedMemorySize, SMEM_BYTES);

    dim3 grid(H_ / RPB, B_, 2);                 // (14, 32, 2)
    conv_kernel<<<grid, BDIM, SMEM_BYTES>>>(x, w, b, out);

    stats_kernel<<<C_, 128>>>(gamma, beta);

    const int n4 = out_size / 4;
    norm_kernel<<<(n4 + 255) / 256, 256>>>(out, n4);
}

// round 4
// speedup vs baseline: 2.3586x; 1.0831x over previous
#include <cuda_runtime.h>

// Problem constants
#define B_   32
#define H_   56
#define W_   56
#define C_   256

// Conv tiling
#define BDIM   256       // 64 channel-pair slots x 4 column teams
#define CHALF  128       // channels per block (z dimension picks half)
#define ROWW   60        // padded smem row length (56 + halo + align)
#define CHPAD  144       // 16 groups * 9 (stride-9 padding -> conflict-free)
#define SLOT   (CHPAD * ROWW)                // floats per row-slot
#define NSLOT  4                             // rolling ring: 1 sync per row
#define SMEM_FLOATS (NSLOT * SLOT)           // 34560
#define SMEM_BYTES  (SMEM_FLOATS * 4)        // 138240
#define RPB    4         // output rows per block

#define NPART  1792      // partials per channel: 14 rowblocks * 32 n * 4 teams

__device__ float g_psum  [C_ * NPART];
__device__ float g_psumsq[C_ * NPART];
__device__ float g_scale[C_];
__device__ float g_shift[C_];

typedef unsigned long long u64;

__device__ __forceinline__ u64 pack2(float lo, float hi) {
    u64 r; asm("mov.b64 %0, {%1, %2};" : "=l"(r) : "f"(lo), "f"(hi)); return r;
}
__device__ __forceinline__ u64 fma2(u64 a, u64 b, u64 c) {
    u64 d; asm("fma.rn.f32x2 %0, %1, %2, %3;" : "=l"(d) : "l"(a), "l"(b), "l"(c)); return d;
}
__device__ __forceinline__ u64 f2u(float2 v) { return *reinterpret_cast<const u64*>(&v); }
__device__ __forceinline__ float u2lo(u64 v) { return __uint_as_float((unsigned)v); }
__device__ __forceinline__ float u2hi(u64 v) { return __uint_as_float((unsigned)(v >> 32)); }

// Load input row hh into ring slot hh%4. 256 threads, 7 float4 each.
__device__ __forceinline__ void load_row(float* smem, const float* __restrict__ x,
                                         int n, int hh, int cbase, int t)
{
    float* slot = smem + (size_t)(hh & 3) * SLOT;
    const float4* src = (const float4*)(x + ((size_t)(n * H_ + hh) * W_) * C_ + cbase);
    #pragma unroll
    for (int it = 0; it < 7; it++) {
        const int f   = t + it * BDIM;
        const int col = f >> 5;
        const int c4  = f & 31;
        const float4 v = __ldg(&src[col * (C_ / 4) + c4]);
        const int g    = c4 >> 1;
        const int ioff = (c4 & 1) * 4;
        float* dst = slot + (size_t)(g * 9 + ioff) * ROWW + (col + 1);
        dst[0 * ROWW] = v.x;  dst[1 * ROWW] = v.y;
        dst[2 * ROWW] = v.z;  dst[3 * ROWW] = v.w;
    }
}

// Zero data columns of ring slot for (virtual OOB) row hh.
__device__ __forceinline__ void zero_row(float* smem, int hh, int t)
{
    float* slot = smem + (size_t)(hh & 3) * SLOT;
    #pragma unroll
    for (int it = 0; it < 7; it++) {
        const int f   = t + it * BDIM;
        const int col = f >> 5;
        const int c4  = f & 31;
        const int g    = c4 >> 1;
        const int ioff = (c4 & 1) * 4;
        float* dst = slot + (size_t)(g * 9 + ioff) * ROWW + (col + 1);
        dst[0 * ROWW] = 0.f;  dst[1 * ROWW] = 0.f;
        dst[2 * ROWW] = 0.f;  dst[3 * ROWW] = 0.f;
    }
}

// ---------------------------------------------------------------------------
// Kernel 1: grouped conv. Each thread computes 2 adjacent out-channels x 14
// cols, all-f32x2 math, 4-slot smem ring (one sync per row).
// grid = (14, 32, 2); block = 256
// Note: bias is omitted on purpose — BatchNorm subtracts the per-channel
// mean, so a per-channel bias cancels exactly.
// ---------------------------------------------------------------------------
__global__ __launch_bounds__(BDIM, 1)
void conv_kernel(const float* __restrict__ x, const float* __restrict__ w,
                 float* __restrict__ y)
{
    extern __shared__ float smem[];
    const int t    = threadIdx.x;
    const int slot = t & 63;               // channel-pair slot
    const int team = t >> 6;               // column team 0..3
    const int gl   = slot >> 2;            // local group 0..15
    const int j    = slot & 3;             // pair index in group
    const int bx   = blockIdx.x;
    const int n    = blockIdx.y;
    const int z    = blockIdx.z;
    const int cbase = z * CHALF;
    const int o0   = cbase + gl * 8 + 2 * j;   // first of channel pair (even)
    const int h0   = bx * RPB;
    const int segbase = team * 14;

    // Zero smem ring once (halo cols + OOB rows)
    {
        float4* s4 = (float4*)smem;
        const float4 z4 = make_float4(0.f, 0.f, 0.f, 0.f);
        for (int idx = t; idx < SMEM_FLOATS / 4; idx += BDIM) s4[idx] = z4;
    }

    // Weights for the channel pair: float2 per tap (HWIO, adjacent channels)
    float2 wp[72];
    #pragma unroll
    for (int k = 0; k < 72; k++)
        wp[k] = __ldg((const float2*)&w[k * C_ + o0]);

    __syncthreads();
    // Prologue: rows h0-1 (zero-init covers OOB), h0, h0+1
    if (h0 > 0) load_row(smem, x, n, h0 - 1, cbase, t);
    load_row(smem, x, n, h0,     cbase, t);
    load_row(smem, x, n, h0 + 1, cbase, t);
    __syncthreads();

    float lsA = 0.f, lqA = 0.f, lsB = 0.f, lqB = 0.f;

    for (int r = 0; r < RPB; r++) {
        const int hr = h0 + r;

        // Prefetch row hr+2 into its free ring slot (LDG overlaps compute)
        if (r < RPB - 1) {
            const int nxt = hr + 2;
            if (nxt < H_)       load_row(smem, x, n, nxt, cbase, t);
            else                zero_row(smem, nxt, t);
        }

        const size_t gbase = (size_t)gl * 9 * ROWW + segbase;
        const float* sl[3];
        sl[0] = smem + (size_t)((hr + 3) & 3) * SLOT + gbase;  // row hr-1
        sl[1] = smem + (size_t)((hr    ) & 3) * SLOT + gbase;  // row hr
        sl[2] = smem + (size_t)((hr + 1) & 3) * SLOT + gbase;  // row hr+1

        u64 accA[7], accB[7];
        #pragma unroll
        for (int p = 0; p < 7; p++) { accA[p] = 0ULL; accB[p] = 0ULL; }

        #pragma unroll
        for (int dh = 0; dh < 3; dh++) {
            #pragma unroll
            for (int ii = 0; ii < 8; ii++) {
                const float* rowp = sl[dh] + ii * ROWW;
                float2 E[8];
                #pragma unroll
                for (int k = 0; k < 8; k++)
                    E[k] = *(const float2*)(rowp + 2 * k);

                const float2 t0 = wp[dh * 24 + 0 + ii];
                const float2 t1 = wp[dh * 24 + 8 + ii];
                const float2 t2 = wp[dh * 24 + 16 + ii];
                const u64 WA0 = pack2(t0.x, t0.x), WB0 = pack2(t0.y, t0.y);
                const u64 WA1 = pack2(t1.x, t1.x), WB1 = pack2(t1.y, t1.y);
                const u64 WA2 = pack2(t2.x, t2.x), WB2 = pack2(t2.y, t2.y);

                #pragma unroll
                for (int p = 0; p < 7; p++) {
                    const u64 X0 = f2u(E[p]);
                    const u64 X1 = pack2(E[p].y, E[p + 1].x);
                    const u64 X2 = f2u(E[p + 1]);
                    accA[p] = fma2(X0, WA0, accA[p]);
                    accA[p] = fma2(X1, WA1, accA[p]);
                    accA[p] = fma2(X2, WA2, accA[p]);
                    accB[p] = fma2(X0, WB0, accB[p]);
                    accB[p] = fma2(X1, WB1, accB[p]);
                    accB[p] = fma2(X2, WB2, accB[p]);
                }
            }
        }

        // Epilogue: coalesced float2 stores (channel pair adjacent)
        float* yrow = y + ((size_t)(n * H_ + hr) * W_) * C_ + o0;
        #pragma unroll
        for (int p = 0; p < 7; p++) {
            const float vA0 = u2lo(accA[p]), vA1 = u2hi(accA[p]);
            const float vB0 = u2lo(accB[p]), vB1 = u2hi(accB[p]);
            *(float2*)(yrow + (size_t)(segbase + 2 * p    ) * C_) = make_float2(vA0, vB0);
            *(float2*)(yrow + (size_t)(segbase + 2 * p + 1) * C_) = make_float2(vA1, vB1);
            lsA += vA0 + vA1;  lqA += vA0 * vA0 + vA1 * vA1;
            lsB += vB0 + vB1;  lqB += vB0 * vB0 + vB1 * vB1;
        }

        __syncthreads();   // single barrier: publishes prefetched row, retires reads
    }

    const int pidx = (bx * 32 + n) * 4 + team;
    g_psum  [(size_t)(o0    ) * NPART + pidx] = lsA;
    g_psumsq[(size_t)(o0    ) * NPART + pidx] = lqA;
    g_psum  [(size_t)(o0 + 1) * NPART + pidx] = lsB;
    g_psumsq[(size_t)(o0 + 1) * NPART + pidx] = lqB;
}

// ---------------------------------------------------------------------------
// Kernel 2: stats finalize — one block per channel
// ---------------------------------------------------------------------------
__global__ void stats_kernel(const float* __restrict__ gamma,
                             const float* __restrict__ beta)
{
    __shared__ float ss[128], sq[128];
    const int o = blockIdx.x;
    const int t = threadIdx.x;

    float s = 0.f, q = 0.f;
    const float* ps = g_psum   + (size_t)o * NPART;
    const float* pq = g_psumsq + (size_t)o * NPART;
    #pragma unroll
    for (int i = t; i < NPART; i += 128) { s += ps[i]; q += pq[i]; }
    ss[t] = s; sq[t] = q;
    __syncthreads();
    #pragma unroll
    for (int st = 64; st > 0; st >>= 1) {
        if (t < st) { ss[t] += ss[t + st]; sq[t] += sq[t + st]; }
        __syncthreads();
    }
    if (t == 0) {
        const float Ninv = 1.0f / (float)(B_ * H_ * W_);
        const float mean = ss[0] * Ninv;
        const float var  = sq[0] * Ninv - mean * mean;
        const float sc   = gamma[o] * rsqrtf(var + 1e-5f);
        g_scale[o] = sc;
        g_shift[o] = beta[o] - mean * sc;
    }
}

// ---------------------------------------------------------------------------
// Kernel 3: in-place normalize + ReLU (float4)
// ---------------------------------------------------------------------------
__global__ void norm_kernel(float* __restrict__ y, int n4)
{
    const int idx = blockIdx.x * blockDim.x + threadIdx.x;
    if (idx >= n4) return;
    float4 v = ((float4*)y)[idx];
    const int c = (idx * 4) & (C_ - 1);
    v.x = fmaxf(v.x * g_scale[c + 0] + g_shift[c + 0], 0.f);
    v.y = fmaxf(v.y * g_scale[c + 1] + g_shift[c + 1], 0.f);
    v.z = fmaxf(v.z * g_scale[c + 2] + g_shift[c + 2], 0.f);
    v.w = fmaxf(v.w * g_scale[c + 3] + g_shift[c + 3], 0.f);
    ((float4*)y)[idx] = v;
}

// ---------------------------------------------------------------------------
extern "C" void kernel_launch(void* const* d_in, const int* in_sizes, int n_in,
                              void* d_out, int out_size)
{
    const float* x     = (const float*)d_in[0];
    const float* w     = (const float*)d_in[1];
    // d_in[2] = bias: mathematically cancelled by BatchNorm (mean subtraction)
    const float* gamma = (const float*)d_in[3];
    const float* beta  = (const float*)d_in[4];
    float* out = (float*)d_out;

    cudaFuncSetAttribute(conv_kernel,
                         cudaFuncAttributeMaxDynamicSharedMemorySize, SMEM_BYTES);

    dim3 grid(H_ / RPB, B_, 2);                 // (14, 32, 2)
    conv_kernel<<<grid, BDIM, SMEM_BYTES>>>(x, w, out);

    stats_kernel<<<C_, 128>>>(gamma, beta);

    const int n4 = out_size / 4;
    norm_kernel<<<(n4 + 255) / 256, 256>>>(out, n4);
}

// round 5
// speedup vs baseline: 2.5262x; 1.0711x over previous
#include <cuda_runtime.h>

// Problem constants
#define B_   32
#define H_   56
#define W_   56
#define C_   256

// Conv tiling
#define BDIM   256       // 64 channel-pair slots x 4 column teams
#define CHALF  128       // channels per block (z dimension picks half)
#define ROWW   58        // padded smem row length (56 + 2 halo), even
#define CHPAD  144       // 16 groups * 9 (stride-9 padding)
#define SLOT   (CHPAD * ROWW)                // 8352 floats per row-slot
#define NSLOT  3                             // 3-slot ring -> 100.2 KB
#define SMEM_FLOATS (NSLOT * SLOT)           // 25056
#define SMEM_BYTES  (SMEM_FLOATS * 4)        // 100224
#define RPB    4         // output rows per block

#define NPART  1792      // partials per channel: 14 rowblocks * 32 n * 4 teams

__device__ float g_psum  [C_ * NPART];
__device__ float g_psumsq[C_ * NPART];
__device__ float g_scale[C_];
__device__ float g_shift[C_];

typedef unsigned long long u64;

__device__ __forceinline__ u64 pack2(float lo, float hi) {
    u64 r; asm("mov.b64 %0, {%1, %2};" : "=l"(r) : "f"(lo), "f"(hi)); return r;
}
__device__ __forceinline__ u64 fma2(u64 a, u64 b, u64 c) {
    u64 d; asm("fma.rn.f32x2 %0, %1, %2, %3;" : "=l"(d) : "l"(a), "l"(b), "l"(c)); return d;
}
__device__ __forceinline__ u64 f2u(float2 v) { return *reinterpret_cast<const u64*>(&v); }
__device__ __forceinline__ float u2lo(u64 v) { return __uint_as_float((unsigned)v); }
__device__ __forceinline__ float u2hi(u64 v) { return __uint_as_float((unsigned)(v >> 32)); }

// Load input row hh into ring slot (hh+3)%3. 256 threads, 7 float4 each.
__device__ __forceinline__ void load_row(float* smem, const float* __restrict__ x,
                                         int n, int hh, int cbase, int t)
{
    float* slot = smem + (size_t)((hh + 3) % 3) * SLOT;
    const float4* src = (const float4*)(x + ((size_t)(n * H_ + hh) * W_) * C_ + cbase);
    #pragma unroll
    for (int it = 0; it < 7; it++) {
        const int f   = t + it * BDIM;
        const int col = f >> 5;
        const int c4  = f & 31;
        const float4 v = __ldg(&src[col * (C_ / 4) + c4]);
        const int g    = c4 >> 1;
        const int ioff = (c4 & 1) * 4;
        float* dst = slot + (size_t)(g * 9 + ioff) * ROWW + (col + 1);
        dst[0 * ROWW] = v.x;  dst[1 * ROWW] = v.y;
        dst[2 * ROWW] = v.z;  dst[3 * ROWW] = v.w;
    }
}

// Zero data columns of ring slot for (virtual OOB) row hh.
__device__ __forceinline__ void zero_row(float* smem, int hh, int t)
{
    float* slot = smem + (size_t)((hh + 3) % 3) * SLOT;
    #pragma unroll
    for (int it = 0; it < 7; it++) {
        const int f   = t + it * BDIM;
        const int col = f >> 5;
        const int c4  = f & 31;
        const int g    = c4 >> 1;
        const int ioff = (c4 & 1) * 4;
        float* dst = slot + (size_t)(g * 9 + ioff) * ROWW + (col + 1);
        dst[0 * ROWW] = 0.f;  dst[1 * ROWW] = 0.f;
        dst[2 * ROWW] = 0.f;  dst[3 * ROWW] = 0.f;
    }
}

// ---------------------------------------------------------------------------
// Kernel 1: grouped conv. 2 adjacent out-channels x 14 cols per thread,
// all-f32x2 math. 3-slot smem ring (100 KB) -> 2 blocks/SM. Weight taps for
// the current dh slice are reloaded per row from L1 (keeps regs < 128).
// grid = (14, 32, 2); block = 256
// Bias omitted: BatchNorm mean-subtraction cancels any per-channel bias.
// ---------------------------------------------------------------------------
__global__ __launch_bounds__(BDIM, 2)
void conv_kernel(const float* __restrict__ x, const float* __restrict__ w,
                 float* __restrict__ y)
{
    extern __shared__ float smem[];
    const int t    = threadIdx.x;
    const int slot = t & 63;               // channel-pair slot
    const int team = t >> 6;               // column team 0..3
    const int gl   = slot >> 2;            // local group 0..15
    const int j    = slot & 3;             // pair index in group
    const int bx   = blockIdx.x;
    const int n    = blockIdx.y;
    const int z    = blockIdx.z;
    const int cbase = z * CHALF;
    const int o0   = cbase + gl * 8 + 2 * j;   // first of channel pair (even)
    const int h0   = bx * RPB;
    const int segbase = team * 14;

    // Zero smem ring once (halo cols + OOB rows)
    {
        float4* s4 = (float4*)smem;
        const float4 z4 = make_float4(0.f, 0.f, 0.f, 0.f);
        for (int idx = t; idx < SMEM_FLOATS / 4; idx += BDIM) s4[idx] = z4;
    }

    __syncthreads();
    // Prologue: rows h0-1 (zero-init covers OOB), h0, h0+1
    if (h0 > 0) load_row(smem, x, n, h0 - 1, cbase, t);
    load_row(smem, x, n, h0,     cbase, t);
    load_row(smem, x, n, h0 + 1, cbase, t);
    __syncthreads();

    float lsA = 0.f, lqA = 0.f, lsB = 0.f, lqB = 0.f;

    for (int r = 0; r < RPB; r++) {
        const int hr = h0 + r;
        const size_t gbase = (size_t)gl * 9 * ROWW + segbase;
        const float* sl[3];
        sl[0] = smem + (size_t)((hr + 2) % 3) * SLOT + gbase;  // row hr-1
        sl[1] = smem + (size_t)((hr    ) % 3) * SLOT + gbase;  // row hr
        sl[2] = smem + (size_t)((hr + 1) % 3) * SLOT + gbase;  // row hr+1

        u64 accA[7], accB[7];
        #pragma unroll
        for (int p = 0; p < 7; p++) { accA[p] = 0ULL; accB[p] = 0ULL; }

        #pragma unroll
        for (int dh = 0; dh < 3; dh++) {
            // Reload this dh-slice's 24 weight taps (float2, adjacent channels).
            // L1-resident after the first row -> cheap; keeps live regs < 128.
            float2 wd[24];
            #pragma unroll
            for (int k = 0; k < 24; k++)
                wd[k] = __ldg((const float2*)&w[(dh * 24 + k) * C_ + o0]);

            #pragma unroll
            for (int ii = 0; ii < 8; ii++) {
                const float* rowp = sl[dh] + ii * ROWW;
                float2 E[8];
                #pragma unroll
                for (int k = 0; k < 8; k++)
                    E[k] = *(const float2*)(rowp + 2 * k);

                const float2 t0 = wd[0 + ii];
                const float2 t1 = wd[8 + ii];
                const float2 t2 = wd[16 + ii];
                const u64 WA0 = pack2(t0.x, t0.x), WB0 = pack2(t0.y, t0.y);
                const u64 WA1 = pack2(t1.x, t1.x), WB1 = pack2(t1.y, t1.y);
                const u64 WA2 = pack2(t2.x, t2.x), WB2 = pack2(t2.y, t2.y);

                #pragma unroll
                for (int p = 0; p < 7; p++) {
                    const u64 X0 = f2u(E[p]);
                    const u64 X1 = pack2(E[p].y, E[p + 1].x);
                    const u64 X2 = f2u(E[p + 1]);
                    accA[p] = fma2(X0, WA0, accA[p]);
                    accA[p] = fma2(X1, WA1, accA[p]);
                    accA[p] = fma2(X2, WA2, accA[p]);
                    accB[p] = fma2(X0, WB0, accB[p]);
                    accB[p] = fma2(X1, WB1, accB[p]);
                    accB[p] = fma2(X2, WB2, accB[p]);
                }
            }
        }

        // Epilogue: coalesced float2 stores (channel pair adjacent)
        float* yrow = y + ((size_t)(n * H_ + hr) * W_) * C_ + o0;
        #pragma unroll
        for (int p = 0; p < 7; p++) {
            const float vA0 = u2lo(accA[p]), vA1 = u2hi(accA[p]);
            const float vB0 = u2lo(accB[p]), vB1 = u2hi(accB[p]);
            *(float2*)(yrow + (size_t)(segbase + 2 * p    ) * C_) = make_float2(vA0, vB0);
            *(float2*)(yrow + (size_t)(segbase + 2 * p + 1) * C_) = make_float2(vA1, vB1);
            lsA += vA0 + vA1;  lqA += vA0 * vA0 + vA1 * vA1;
            lsB += vB0 + vB1;  lqB += vB0 * vB0 + vB1 * vB1;
        }

        __syncthreads();   // all reads of the ring retired
        if (r < RPB - 1) {
            const int nxt = hr + 2;
            if (nxt < H_)       load_row(smem, x, n, nxt, cbase, t);
            else                zero_row(smem, nxt, t);
        }
        __syncthreads();   // new row published
    }

    const int pidx = (bx * 32 + n) * 4 + team;
    g_psum  [(size_t)(o0    ) * NPART + pidx] = lsA;
    g_psumsq[(size_t)(o0    ) * NPART + pidx] = lqA;
    g_psum  [(size_t)(o0 + 1) * NPART + pidx] = lsB;
    g_psumsq[(size_t)(o0 + 1) * NPART + pidx] = lqB;
}

// ---------------------------------------------------------------------------
// Kernel 2: stats finalize — one block per channel
// ---------------------------------------------------------------------------
__global__ void stats_kernel(const float* __restrict__ gamma,
                             const float* __restrict__ beta)
{
    __shared__ float ss[128], sq[128];
    const int o = blockIdx.x;
    const int t = threadIdx.x;

    float s = 0.f, q = 0.f;
    const float* ps = g_psum   + (size_t)o * NPART;
    const float* pq = g_psumsq + (size_t)o * NPART;
    #pragma unroll
    for (int i = t; i < NPART; i += 128) { s += ps[i]; q += pq[i]; }
    ss[t] = s; sq[t] = q;
    __syncthreads();
    #pragma unroll
    for (int st = 64; st > 0; st >>= 1) {
        if (t < st) { ss[t] += ss[t + st]; sq[t] += sq[t + st]; }
        __syncthreads();
    }
    if (t == 0) {
        const float Ninv = 1.0f / (float)(B_ * H_ * W_);
        const float mean = ss[0] * Ninv;
        const float var  = sq[0] * Ninv - mean * mean;
        const float sc   = gamma[o] * rsqrtf(var + 1e-5f);
        g_scale[o] = sc;
        g_shift[o] = beta[o] - mean * sc;
    }
}

// ---------------------------------------------------------------------------
// Kernel 3: in-place normalize + ReLU (float4)
// ---------------------------------------------------------------------------
__global__ void norm_kernel(float* __restrict__ y, int n4)
{
    const int idx = blockIdx.x * blockDim.x + threadIdx.x;
    if (idx >= n4) return;
    float4 v = ((float4*)y)[idx];
    const int c = (idx * 4) & (C_ - 1);
    v.x = fmaxf(v.x * g_scale[c + 0] + g_shift[c + 0], 0.f);
    v.y = fmaxf(v.y * g_scale[c + 1] + g_shift[c + 1], 0.f);
    v.z = fmaxf(v.z * g_scale[c + 2] + g_shift[c + 2], 0.f);
    v.w = fmaxf(v.w * g_scale[c + 3] + g_shift[c + 3], 0.f);
    ((float4*)y)[idx] = v;
}

// ---------------------------------------------------------------------------
extern "C" void kernel_launch(void* const* d_in, const int* in_sizes, int n_in,
                              void* d_out, int out_size)
{
    const float* x     = (const float*)d_in[0];
    const float* w     = (const float*)d_in[1];
    // d_in[2] = bias: cancelled exactly by BatchNorm mean subtraction
    const float* gamma = (const float*)d_in[3];
    const float* beta  = (const float*)d_in[4];
    float* out = (float*)d_out;

    cudaFuncSetAttribute(conv_kernel,
                         cudaFuncAttributeMaxDynamicSharedMemorySize, SMEM_BYTES);

    dim3 grid(H_ / RPB, B_, 2);                 // (14, 32, 2)
    conv_kernel<<<grid, BDIM, SMEM_BYTES>>>(x, w, out);

    stats_kernel<<<C_, 128>>>(gamma, beta);

    const int n4 = out_size / 4;
    norm_kernel<<<(n4 + 255) / 256, 256>>>(out, n4);
}

// round 6
// speedup vs baseline: 2.6206x; 1.0374x over previous
#include <cuda_runtime.h>

// Problem constants
#define B_   32
#define H_   56
#define W_   56
#define C_   256

// Conv tiling: 64 channels per block, 2 row-subteams x 4 col-teams x 32 pairs
#define BDIM   256
#define CQTR   64        // channels per block
#define NGRP   8         // groups per block
#define ROWW   58        // padded smem row length (56 + 2 halo), even
#define CHPAD  (NGRP * 9)                    // 72, stride-9 padding
#define SLOT   (CHPAD * ROWW)                // 4176 floats per row-slot
#define NSLOT  4                             // ring: rows r-1..r+2
#define SMEM_FLOATS (NSLOT * SLOT)           // 16704
#define SMEM_BYTES  (SMEM_FLOATS * 4)        // 66816 -> 3 blocks/SM
#define RPB    8         // output rows per block (2 rows x 4 steps)

#define NPART  1792      // 7 rowblocks * 32 n * 4 teams * 2 rowteams

__device__ float g_psum  [C_ * NPART];
__device__ float g_psumsq[C_ * NPART];
__device__ float g_scale[C_];
__device__ float g_shift[C_];

typedef unsigned long long u64;

__device__ __forceinline__ u64 pack2(float lo, float hi) {
    u64 r; asm("mov.b64 %0, {%1, %2};" : "=l"(r) : "f"(lo), "f"(hi)); return r;
}
__device__ __forceinline__ u64 fma2(u64 a, u64 b, u64 c) {
    u64 d; asm("fma.rn.f32x2 %0, %1, %2, %3;" : "=l"(d) : "l"(a), "l"(b), "l"(c)); return d;
}
__device__ __forceinline__ u64 f2u(float2 v) { return *reinterpret_cast<const u64*>(&v); }
__device__ __forceinline__ float u2lo(u64 v) { return __uint_as_float((unsigned)v); }
__device__ __forceinline__ float u2hi(u64 v) { return __uint_as_float((unsigned)(v >> 32)); }

__device__ __forceinline__ int slot_of(int row) { return (row + 4) & 3; }

// Load input row hh (64 channels starting at cbase) into its ring slot.
// 56 cols x 16 float4 = 896 float4, 256 threads -> 3.5 iterations.
__device__ __forceinline__ void load_row(float* smem, const float* __restrict__ x,
                                         int n, int hh, int cbase, int t)
{
    float* slot = smem + (size_t)slot_of(hh) * SLOT;
    const float4* src = (const float4*)(x + ((size_t)(n * H_ + hh) * W_) * C_ + cbase);
    #pragma unroll
    for (int it = 0; it < 4; it++) {
        const int f = t + it * BDIM;
        if (f < 56 * 16) {
            const int col = f >> 4;            // 0..55
            const int c4  = f & 15;            // 0..15 (16 float4 = 64 ch)
            const float4 v = __ldg(&src[col * (C_ / 4) + c4]);
            const int g    = c4 >> 1;          // local group 0..7
            const int ioff = (c4 & 1) * 4;
            float* dst = slot + (size_t)(g * 9 + ioff) * ROWW + (col + 1);
            dst[0 * ROWW] = v.x;  dst[1 * ROWW] = v.y;
            dst[2 * ROWW] = v.z;  dst[3 * ROWW] = v.w;
        }
    }
}

// Zero data columns of ring slot for (virtual OOB) row hh.
__device__ __forceinline__ void zero_row(float* smem, int hh, int t)
{
    float* slot = smem + (size_t)slot_of(hh) * SLOT;
    #pragma unroll
    for (int it = 0; it < 4; it++) {
        const int f = t + it * BDIM;
        if (f < 56 * 16) {
            const int col = f >> 4;
            const int c4  = f & 15;
            const int g    = c4 >> 1;
            const int ioff = (c4 & 1) * 4;
            float* dst = slot + (size_t)(g * 9 + ioff) * ROWW + (col + 1);
            dst[0 * ROWW] = 0.f;  dst[1 * ROWW] = 0.f;
            dst[2 * ROWW] = 0.f;  dst[3 * ROWW] = 0.f;
        }
    }
}

// ---------------------------------------------------------------------------
// Kernel 1: grouped conv. 2 adjacent out-channels x 14 cols per thread,
// all-f32x2 math. 64 channels/block, 4-slot ring (66.8 KB) -> 3 blocks/SM.
// Two row-subteams compute rows r and r+1 of the shared window concurrently.
// grid = (7, 32, 4); block = 256. Bias omitted (cancelled by BN mean-sub).
// ---------------------------------------------------------------------------
__global__ __launch_bounds__(BDIM, 3)
void conv_kernel(const float* __restrict__ x, const float* __restrict__ w,
                 float* __restrict__ y)
{
    extern __shared__ float smem[];
    const int t       = threadIdx.x;
    const int rowteam = t >> 7;            // 0/1
    const int tt      = t & 127;
    const int team    = tt >> 5;           // col team 0..3
    const int ps      = tt & 31;           // pair slot
    const int gl      = ps >> 2;           // local group 0..7
    const int j       = ps & 3;            // pair in group
    const int bx      = blockIdx.x;        // 0..6
    const int n       = blockIdx.y;
    const int z       = blockIdx.z;        // 0..3
    const int cbase   = z * CQTR;
    const int o0      = cbase + gl * 8 + 2 * j;
    const int h0      = bx * RPB;
    const int segbase = team * 14;

    // Zero smem ring (halo cols + virtual OOB rows)
    {
        float4* s4 = (float4*)smem;
        const float4 z4 = make_float4(0.f, 0.f, 0.f, 0.f);
        #pragma unroll
        for (int idx = t; idx < SMEM_FLOATS / 4; idx += BDIM) s4[idx] = z4;
    }
    __syncthreads();

    // Prologue: rows h0-1 (zeros if OOB), h0, h0+1, h0+2 (all < 56)
    if (h0 > 0) load_row(smem, x, n, h0 - 1, cbase, t);
    load_row(smem, x, n, h0,     cbase, t);
    load_row(smem, x, n, h0 + 1, cbase, t);
    load_row(smem, x, n, h0 + 2, cbase, t);
    __syncthreads();

    float lsA = 0.f, lqA = 0.f, lsB = 0.f, lqB = 0.f;
    const size_t gbase = (size_t)gl * 9 * ROWW + segbase;

    #pragma unroll
    for (int s = 0; s < 4; s++) {
        const int hr = h0 + 2 * s + rowteam;     // this subteam's output row

        const float* sl0 = smem + (size_t)slot_of(hr - 1) * SLOT + gbase;
        const float* sl1 = smem + (size_t)slot_of(hr    ) * SLOT + gbase;
        const float* sl2 = smem + (size_t)slot_of(hr + 1) * SLOT + gbase;

        u64 accA[7], accB[7];
        #pragma unroll
        for (int p = 0; p < 7; p++) { accA[p] = 0ULL; accB[p] = 0ULL; }

        #pragma unroll
        for (int dh = 0; dh < 3; dh++) {
            const float* slr = (dh == 0) ? sl0 : (dh == 1) ? sl1 : sl2;
            #pragma unroll
            for (int ii = 0; ii < 8; ii++) {
                // 3 taps for this (dh, ii), channel pair -> 6 floats (L1 hits)
                const float2 t0 = __ldg((const float2*)&w[(dh * 24 +      ii) * C_ + o0]);
                const float2 t1 = __ldg((const float2*)&w[(dh * 24 +  8 + ii) * C_ + o0]);
                const float2 t2 = __ldg((const float2*)&w[(dh * 24 + 16 + ii) * C_ + o0]);
                const u64 WA0 = pack2(t0.x, t0.x), WB0 = pack2(t0.y, t0.y);
                const u64 WA1 = pack2(t1.x, t1.x), WB1 = pack2(t1.y, t1.y);
                const u64 WA2 = pack2(t2.x, t2.x), WB2 = pack2(t2.y, t2.y);

                const float* rowp = slr + ii * ROWW;
                float2 E[8];
                #pragma unroll
                for (int k = 0; k < 8; k++)
                    E[k] = *(const float2*)(rowp + 2 * k);

                #pragma unroll
                for (int p = 0; p < 7; p++) {
                    const u64 X0 = f2u(E[p]);
                    const u64 X1 = pack2(E[p].y, E[p + 1].x);
                    const u64 X2 = f2u(E[p + 1]);
                    accA[p] = fma2(X0, WA0, accA[p]);
                    accA[p] = fma2(X1, WA1, accA[p]);
                    accA[p] = fma2(X2, WA2, accA[p]);
                    accB[p] = fma2(X0, WB0, accB[p]);
                    accB[p] = fma2(X1, WB1, accB[p]);
                    accB[p] = fma2(X2, WB2, accB[p]);
                }
            }
        }

        // Coalesced float2 stores (channel pair adjacent; warp = 64 adj ch)
        float* yrow = y + ((size_t)(n * H_ + hr) * W_) * C_ + o0;
        #pragma unroll
        for (int p = 0; p < 7; p++) {
            const float vA0 = u2lo(accA[p]), vA1 = u2hi(accA[p]);
            const float vB0 = u2lo(accB[p]), vB1 = u2hi(accB[p]);
            *(float2*)(yrow + (size_t)(segbase + 2 * p    ) * C_) = make_float2(vA0, vB0);
            *(float2*)(yrow + (size_t)(segbase + 2 * p + 1) * C_) = make_float2(vA1, vB1);
            lsA += vA0 + vA1;  lqA += vA0 * vA0 + vA1 * vA1;
            lsB += vB0 + vB1;  lqB += vB0 * vB0 + vB1 * vB1;
        }

        __syncthreads();    // window reads retired
        if (s < 3) {
            const int r1 = h0 + 2 * s + 3;       // always < 56
            const int r2 = h0 + 2 * s + 4;       // may be 56 (OOB)
            load_row(smem, x, n, r1, cbase, t);
            if (r2 < H_) load_row(smem, x, n, r2, cbase, t);
            else         zero_row(smem, r2, t);
        }
        __syncthreads();    // new rows published
    }

    const int pidx = (((bx * 32 + n) * 4) + team) * 2 + rowteam;
    g_psum  [(size_t)(o0    ) * NPART + pidx] = lsA;
    g_psumsq[(size_t)(o0    ) * NPART + pidx] = lqA;
    g_psum  [(size_t)(o0 + 1) * NPART + pidx] = lsB;
    g_psumsq[(size_t)(o0 + 1) * NPART + pidx] = lqB;
}

// ---------------------------------------------------------------------------
// Kernel 2: stats finalize — one block per channel
// ---------------------------------------------------------------------------
__global__ void stats_kernel(const float* __restrict__ gamma,
                             const float* __restrict__ beta)
{
    __shared__ float ss[128], sq[128];
    const int o = blockIdx.x;
    const int t = threadIdx.x;

    float s = 0.f, q = 0.f;
    const float* ps = g_psum   + (size_t)o * NPART;
    const float* pq = g_psumsq + (size_t)o * NPART;
    #pragma unroll
    for (int i = t; i < NPART; i += 128) { s += ps[i]; q += pq[i]; }
    ss[t] = s; sq[t] = q;
    __syncthreads();
    #pragma unroll
    for (int st = 64; st > 0; st >>= 1) {
        if (t < st) { ss[t] += ss[t + st]; sq[t] += sq[t + st]; }
        __syncthreads();
    }
    if (t == 0) {
        const float Ninv = 1.0f / (float)(B_ * H_ * W_);
        const float mean = ss[0] * Ninv;
        const float var  = sq[0] * Ninv - mean * mean;
        const float sc   = gamma[o] * rsqrtf(var + 1e-5f);
        g_scale[o] = sc;
        g_shift[o] = beta[o] - mean * sc;
    }
}

// ---------------------------------------------------------------------------
// Kernel 3: in-place normalize + ReLU (float4)
// ---------------------------------------------------------------------------
__global__ void norm_kernel(float* __restrict__ y, int n4)
{
    const int idx = blockIdx.x * blockDim.x + threadIdx.x;
    if (idx >= n4) return;
    float4 v = ((float4*)y)[idx];
    const int c = (idx * 4) & (C_ - 1);
    v.x = fmaxf(v.x * g_scale[c + 0] + g_shift[c + 0], 0.f);
    v.y = fmaxf(v.y * g_scale[c + 1] + g_shift[c + 1], 0.f);
    v.z = fmaxf(v.z * g_scale[c + 2] + g_shift[c + 2], 0.f);
    v.w = fmaxf(v.w * g_scale[c + 3] + g_shift[c + 3], 0.f);
    ((float4*)y)[idx] = v;
}

// ---------------------------------------------------------------------------
extern "C" void kernel_launch(void* const* d_in, const int* in_sizes, int n_in,
                              void* d_out, int out_size)
{
    const float* x     = (const float*)d_in[0];
    const float* w     = (const float*)d_in[1];
    // d_in[2] = bias: cancelled exactly by BatchNorm mean subtraction
    const float* gamma = (const float*)d_in[3];
    const float* beta  = (const float*)d_in[4];
    float* out = (float*)d_out;

    cudaFuncSetAttribute(conv_kernel,
                         cudaFuncAttributeMaxDynamicSharedMemorySize, SMEM_BYTES);

    dim3 grid(H_ / RPB, B_, 4);                 // (7, 32, 4)
    conv_kernel<<<grid, BDIM, SMEM_BYTES>>>(x, w, out);

    stats_kernel<<<C_, 128>>>(gamma, beta);

    const int n4 = out_size / 4;
    norm_kernel<<<(n4 + 255) / 256, 256>>>(out, n4);
}

// round 7
// speedup vs baseline: 2.6435x; 1.0087x over previous
#include <cuda_runtime.h>

// Problem constants
#define B_   32
#define H_   56
#define W_   56
#define C_   256

// Conv tiling: 64 channels per block, 2 row-subteams x 4 col-teams x 32 pairs
#define BDIM   256
#define CQTR   64        // channels per block
#define NGRP   8         // groups per block
#define ROWW   58        // padded smem row length (56 + 2 halo)
#define CHPAD  (NGRP * 9)                    // 72, stride-9 padding
#define SLOT   (CHPAD * ROWW)                // 4176 floats per row-slot
#define NSLOT  6                             // ring: reads r-1..r+2, writes r+3,r+4
#define SMEM_FLOATS (NSLOT * SLOT)           // 25056
#define SMEM_BYTES  (SMEM_FLOATS * 4)        // 100224 -> 2 blocks/SM
#define RPB    8         // output rows per block (2 rows x 4 steps)

#define NPART  1792      // 7 rowblocks * 32 n * 4 teams * 2 rowteams

__device__ float g_psum  [C_ * NPART];
__device__ float g_psumsq[C_ * NPART];
__device__ float g_scale[C_];
__device__ float g_shift[C_];

typedef unsigned long long u64;

__device__ __forceinline__ u64 pack2(float lo, float hi) {
    u64 r; asm("mov.b64 %0, {%1, %2};" : "=l"(r) : "f"(lo), "f"(hi)); return r;
}
__device__ __forceinline__ u64 fma2(u64 a, u64 b, u64 c) {
    u64 d; asm("fma.rn.f32x2 %0, %1, %2, %3;" : "=l"(d) : "l"(a), "l"(b), "l"(c)); return d;
}
__device__ __forceinline__ u64 f2u(float2 v) { return *reinterpret_cast<const u64*>(&v); }
__device__ __forceinline__ float u2lo(u64 v) { return __uint_as_float((unsigned)v); }
__device__ __forceinline__ float u2hi(u64 v) { return __uint_as_float((unsigned)(v >> 32)); }

__device__ __forceinline__ int slot_of(int row) { return (row + 6) % 6; }

// Direct LDG->STS load of one input row (prologue only).
__device__ __forceinline__ void load_row(float* smem, const float* __restrict__ x,
                                         int n, int hh, int cbase, int t)
{
    float* slot = smem + (size_t)slot_of(hh) * SLOT;
    const float4* src = (const float4*)(x + ((size_t)(n * H_ + hh) * W_) * C_ + cbase);
    #pragma unroll
    for (int it = 0; it < 4; it++) {
        const int f = t + it * BDIM;
        if (f < 56 * 16) {
            const int col = f >> 4;
            const int c4  = f & 15;
            const float4 v = __ldg(&src[col * (C_ / 4) + c4]);
            const int g    = c4 >> 1;
            const int ioff = (c4 & 1) * 4;
            float* dst = slot + (size_t)(g * 9 + ioff) * ROWW + (col + 1);
            dst[0 * ROWW] = v.x;  dst[1 * ROWW] = v.y;
            dst[2 * ROWW] = v.z;  dst[3 * ROWW] = v.w;
        }
    }
}

// ---------------------------------------------------------------------------
// Kernel 1: grouped conv. 2 adjacent out-channels x 14 cols per thread,
// all-f32x2 math. 6-slot smem ring: prefetch next 2 rows into REGISTERS at
// step top, compute, STS at step bottom, ONE barrier per step (DRAM latency
// hidden behind compute; no exposed load phase between barriers).
// grid = (7, 32, 4); block = 256. Bias omitted (cancelled by BN mean-sub).
// ---------------------------------------------------------------------------
__global__ __launch_bounds__(BDIM, 2)
void conv_kernel(const float* __restrict__ x, const float* __restrict__ w,
                 float* __restrict__ y)
{
    extern __shared__ float smem[];
    const int t       = threadIdx.x;
    const int rowteam = t >> 7;            // 0/1
    const int tt      = t & 127;
    const int team    = tt >> 5;           // col team 0..3
    const int ps      = tt & 31;           // pair slot
    const int gl      = ps >> 2;           // local group 0..7
    const int j       = ps & 3;            // pair in group
    const int bx      = blockIdx.x;        // 0..6
    const int n       = blockIdx.y;
    const int z       = blockIdx.z;        // 0..3
    const int cbase   = z * CQTR;
    const int o0      = cbase + gl * 8 + 2 * j;
    const int h0      = bx * RPB;
    const int segbase = team * 14;

    // Zero smem ring (halo cols + virtual OOB rows like row -1)
    {
        float4* s4 = (float4*)smem;
        const float4 z4 = make_float4(0.f, 0.f, 0.f, 0.f);
        for (int idx = t; idx < SMEM_FLOATS / 4; idx += BDIM) s4[idx] = z4;
    }
    __syncthreads();

    // Prologue: rows h0-1 (zeros if OOB), h0, h0+1, h0+2
    if (h0 > 0) load_row(smem, x, n, h0 - 1, cbase, t);
    load_row(smem, x, n, h0,     cbase, t);
    load_row(smem, x, n, h0 + 1, cbase, t);
    load_row(smem, x, n, h0 + 2, cbase, t);
    __syncthreads();

    float lsA = 0.f, lqA = 0.f, lsB = 0.f, lqB = 0.f;
    const size_t gbase = (size_t)gl * 9 * ROWW + segbase;

    #pragma unroll 1
    for (int s = 0; s < 4; s++) {
        const int hr = h0 + 2 * s + rowteam;     // this subteam's output row

        // ---- Prefetch rows 2s+3, 2s+4 into registers (LDGs issue now, ----
        // ---- data consumed by STS after compute; nothing here blocks)  ----
        float4 pf[7];
        const int r1 = h0 + 2 * s + 3;           // always < 56
        const int r2 = h0 + 2 * s + 4;           // may be 56 (OOB)
        const bool do_pre = (s < 3);
        if (do_pre) {
            const float4* src1 = (const float4*)(x + ((size_t)(n * H_ + r1) * W_) * C_ + cbase);
            const float4* src2 = (const float4*)(x + ((size_t)(n * H_ + r2) * W_) * C_ + cbase);
            #pragma unroll
            for (int it = 0; it < 7; it++) {
                const int f  = t + it * BDIM;          // 0..1791
                const bool first = (f < 896);
                const int fl = first ? f : f - 896;
                const int col = fl >> 4;
                const int c4  = fl & 15;
                if (first)          pf[it] = __ldg(&src1[col * (C_ / 4) + c4]);
                else if (r2 < H_)   pf[it] = __ldg(&src2[col * (C_ / 4) + c4]);
                else                pf[it] = make_float4(0.f, 0.f, 0.f, 0.f);
            }
        }

        // ---- Compute output row hr ----
        const float* sl0 = smem + (size_t)slot_of(hr - 1) * SLOT + gbase;
        const float* sl1 = smem + (size_t)slot_of(hr    ) * SLOT + gbase;
        const float* sl2 = smem + (size_t)slot_of(hr + 1) * SLOT + gbase;

        u64 accA[7], accB[7];
        #pragma unroll
        for (int p = 0; p < 7; p++) { accA[p] = 0ULL; accB[p] = 0ULL; }

        #pragma unroll
        for (int dh = 0; dh < 3; dh++) {
            const float* slr = (dh == 0) ? sl0 : (dh == 1) ? sl1 : sl2;
            #pragma unroll
            for (int ii = 0; ii < 8; ii++) {
                const float2 t0 = __ldg((const float2*)&w[(dh * 24 +      ii) * C_ + o0]);
                const float2 t1 = __ldg((const float2*)&w[(dh * 24 +  8 + ii) * C_ + o0]);
                const float2 t2 = __ldg((const float2*)&w[(dh * 24 + 16 + ii) * C_ + o0]);
                const u64 WA0 = pack2(t0.x, t0.x), WB0 = pack2(t0.y, t0.y);
                const u64 WA1 = pack2(t1.x, t1.x), WB1 = pack2(t1.y, t1.y);
                const u64 WA2 = pack2(t2.x, t2.x), WB2 = pack2(t2.y, t2.y);

                const float* rowp = slr + ii * ROWW;
                float2 E[8];
                #pragma unroll
                for (int k = 0; k < 8; k++)
                    E[k] = *(const float2*)(rowp + 2 * k);

                #pragma unroll
                for (int p = 0; p < 7; p++) {
                    const u64 X0 = f2u(E[p]);
                    const u64 X1 = pack2(E[p].y, E[p + 1].x);
                    const u64 X2 = f2u(E[p + 1]);
                    accA[p] = fma2(X0, WA0, accA[p]);
                    accA[p] = fma2(X1, WA1, accA[p]);
                    accA[p] = fma2(X2, WA2, accA[p]);
                    accB[p] = fma2(X0, WB0, accB[p]);
                    accB[p] = fma2(X1, WB1, accB[p]);
                    accB[p] = fma2(X2, WB2, accB[p]);
                }
            }
        }

        // ---- Epilogue: coalesced float2 stores + running stats ----
        float* yrow = y + ((size_t)(n * H_ + hr) * W_) * C_ + o0;
        #pragma unroll
        for (int p = 0; p < 7; p++) {
            const float vA0 = u2lo(accA[p]), vA1 = u2hi(accA[p]);
            const float vB0 = u2lo(accB[p]), vB1 = u2hi(accB[p]);
            *(float2*)(yrow + (size_t)(segbase + 2 * p    ) * C_) = make_float2(vA0, vB0);
            *(float2*)(yrow + (size_t)(segbase + 2 * p + 1) * C_) = make_float2(vA1, vB1);
            lsA += vA0 + vA1;  lqA += vA0 * vA0 + vA1 * vA1;
            lsB += vB0 + vB1;  lqB += vB0 * vB0 + vB1 * vB1;
        }

        // ---- Drain prefetch to smem (slots 2s+3, 2s+4 mod 6: not read ----
        // ---- this step; previous step's barrier retired older readers) ----
        if (do_pre) {
            #pragma unroll
            for (int it = 0; it < 7; it++) {
                const int f  = t + it * BDIM;
                const bool first = (f < 896);
                const int fl = first ? f : f - 896;
                const int col = fl >> 4;
                const int c4  = fl & 15;
                const int rr  = first ? r1 : r2;
                float* slotp = smem + (size_t)slot_of(rr) * SLOT;
                const int g    = c4 >> 1;
                const int ioff = (c4 & 1) * 4;
                float* dst = slotp + (size_t)(g * 9 + ioff) * ROWW + (col + 1);
                dst[0 * ROWW] = pf[it].x;  dst[1 * ROWW] = pf[it].y;
                dst[2 * ROWW] = pf[it].z;  dst[3 * ROWW] = pf[it].w;
            }
        }

        __syncthreads();   // single barrier: publishes new rows, retires reads
    }

    const int pidx = (((bx * 32 + n) * 4) + team) * 2 + rowteam;
    g_psum  [(size_t)(o0    ) * NPART + pidx] = lsA;
    g_psumsq[(size_t)(o0    ) * NPART + pidx] = lqA;
    g_psum  [(size_t)(o0 + 1) * NPART + pidx] = lsB;
    g_psumsq[(size_t)(o0 + 1) * NPART + pidx] = lqB;
}

// ---------------------------------------------------------------------------
// Kernel 2: stats finalize — one block per channel
// ---------------------------------------------------------------------------
__global__ void stats_kernel(const float* __restrict__ gamma,
                             const float* __restrict__ beta)
{
    __shared__ float ss[128], sq[128];
    const int o = blockIdx.x;
    const int t = threadIdx.x;

    float s = 0.f, q = 0.f;
    const float* ps = g_psum   + (size_t)o * NPART;
    const float* pq = g_psumsq + (size_t)o * NPART;
    #pragma unroll
    for (int i = t; i < NPART; i += 128) { s += ps[i]; q += pq[i]; }
    ss[t] = s; sq[t] = q;
    __syncthreads();
    #pragma unroll
    for (int st = 64; st > 0; st >>= 1) {
        if (t < st) { ss[t] += ss[t + st]; sq[t] += sq[t + st]; }
        __syncthreads();
    }
    if (t == 0) {
        const float Ninv = 1.0f / (float)(B_ * H_ * W_);
        const float mean = ss[0] * Ninv;
        const float var  = sq[0] * Ninv - mean * mean;
        const float sc   = gamma[o] * rsqrtf(var + 1e-5f);
        g_scale[o] = sc;
        g_shift[o] = beta[o] - mean * sc;
    }
}

// ---------------------------------------------------------------------------
// Kernel 3: in-place normalize + ReLU (float4)
// ---------------------------------------------------------------------------
__global__ void norm_kernel(float* __restrict__ y, int n4)
{
    const int idx = blockIdx.x * blockDim.x + threadIdx.x;
    if (idx >= n4) return;
    float4 v = ((float4*)y)[idx];
    const int c = (idx * 4) & (C_ - 1);
    v.x = fmaxf(v.x * g_scale[c + 0] + g_shift[c + 0], 0.f);
    v.y = fmaxf(v.y * g_scale[c + 1] + g_shift[c + 1], 0.f);
    v.z = fmaxf(v.z * g_scale[c + 2] + g_shift[c + 2], 0.f);
    v.w = fmaxf(v.w * g_scale[c + 3] + g_shift[c + 3], 0.f);
    ((float4*)y)[idx] = v;
}

// ---------------------------------------------------------------------------
extern "C" void kernel_launch(void* const* d_in, const int* in_sizes, int n_in,
                              void* d_out, int out_size)
{
    const float* x     = (const float*)d_in[0];
    const float* w     = (const float*)d_in[1];
    // d_in[2] = bias: cancelled exactly by BatchNorm mean subtraction
    const float* gamma = (const float*)d_in[3];
    const float* beta  = (const float*)d_in[4];
    float* out = (float*)d_out;

    cudaFuncSetAttribute(conv_kernel,
                         cudaFuncAttributeMaxDynamicSharedMemorySize, SMEM_BYTES);

    dim3 grid(H_ / RPB, B_, 4);                 // (7, 32, 4)
    conv_kernel<<<grid, BDIM, SMEM_BYTES>>>(x, w, out);

    stats_kernel<<<C_, 128>>>(gamma, beta);

    const int n4 = out_size / 4;
    norm_kernel<<<(n4 + 255) / 256, 256>>>(out, n4);
}